// round 12
// baseline (speedup 1.0000x reference)
#include <cuda_runtime.h>
#include <cuda_fp16.h>
#include <cstdint>

#define N_NODES 100000
#define E_EDGES 1600000
#define IN_DIM  128
#define KH      8
#define DH      16
#define F       128
#define NEG_SLOPE 0.2f
#define SCAN_B  1024
#define NBLK    ((N_NODES + SCAN_B - 1) / SCAN_B)   // 98
#define CAP     128

// ---------------- scratch ----------------
__device__ __half g_feat_h[N_NODES * F];
__device__ float  g_el[N_NODES * KH];
__device__ float  g_er[N_NODES * KH];
__device__ int    g_deg[N_NODES];
__device__ int    g_off[N_NODES + 1];
__device__ int    g_rank[E_EDGES];
__device__ int    g_psrc[E_EDGES];
__device__ unsigned long long g_desc[NBLK];

// ---------------- P1: GEMM feat @ W, 8x8 tile, cp.async W, FFMA2 ----------
#define BKC 16   // k-chunk
__global__ __launch_bounds__(128) void gemm_kernel(const float* __restrict__ feat,
                                                   const float* __restrict__ W,
                                                   const float* __restrict__ attn_l,
                                                   const float* __restrict__ attn_r) {
    __shared__ __align__(16) float sXT[2][BKC][68];    // [buf][k][row] transposed
    __shared__ __align__(16) float sW[2][BKC][F];      // [buf][k][col]
    const int t  = threadIdx.x;
    const int tr = t >> 4;    // 0..7  -> rows tr*8..+7
    const int tc = t & 15;    // 0..15 -> cols tc*8..+7
    const int row0 = blockIdx.x * 64;

    // X load map: 2 float4 per thread per chunk
    const int xr0 = t >> 2,         xc0 = t & 3;
    const int xr1 = (t + 128) >> 2, xc1 = (t + 128) & 3;
    int g0 = row0 + xr0; if (g0 >= N_NODES) g0 = N_NODES - 1;
    int g1 = row0 + xr1; if (g1 >= N_NODES) g1 = N_NODES - 1;

    // prologue: chunk 0
    float4 xv0 = *(const float4*)&feat[g0 * IN_DIM + xc0 * 4];
    float4 xv1 = *(const float4*)&feat[g1 * IN_DIM + xc1 * 4];
#pragma unroll
    for (int i = 0; i < 4; i++) {
        int idx = t + i * 128;
        int r = idx >> 5, c4 = idx & 31;
        unsigned sa = (unsigned)__cvta_generic_to_shared(&sW[0][r][c4 * 4]);
        asm volatile("cp.async.ca.shared.global [%0], [%1], 16;"
                     :: "r"(sa), "l"(&W[r * F + c4 * 4]));
    }
    asm volatile("cp.async.commit_group;");
#pragma unroll
    for (int j = 0; j < 4; j++) {
        sXT[0][xc0 * 4 + j][xr0] = ((const float*)&xv0)[j];
        sXT[0][xc1 * 4 + j][xr1] = ((const float*)&xv1)[j];
    }
    asm volatile("cp.async.wait_group 0;" ::: "memory");
    __syncthreads();

    unsigned long long acc[8][4];
#pragma unroll
    for (int r = 0; r < 8; r++)
#pragma unroll
        for (int c = 0; c < 4; c++) acc[r][c] = 0ULL;

#pragma unroll
    for (int ch = 0; ch < IN_DIM / BKC; ch++) {
        const int cur = ch & 1;
        float4 nx0, nx1;
        if (ch < IN_DIM / BKC - 1) {
            int kb = (ch + 1) * BKC;
            nx0 = *(const float4*)&feat[g0 * IN_DIM + kb + xc0 * 4];
            nx1 = *(const float4*)&feat[g1 * IN_DIM + kb + xc1 * 4];
#pragma unroll
            for (int i = 0; i < 4; i++) {
                int idx = t + i * 128;
                int r = idx >> 5, c4 = idx & 31;
                unsigned sa = (unsigned)__cvta_generic_to_shared(&sW[cur ^ 1][r][c4 * 4]);
                asm volatile("cp.async.ca.shared.global [%0], [%1], 16;"
                             :: "r"(sa), "l"(&W[(kb + r) * F + c4 * 4]));
            }
            asm volatile("cp.async.commit_group;");
        }

#pragma unroll
        for (int kk = 0; kk < BKC; kk++) {
            float4 w0 = *(const float4*)&sW[cur][kk][tc * 8];
            float4 w1 = *(const float4*)&sW[cur][kk][tc * 8 + 4];
            float4 xa = *(const float4*)&sXT[cur][kk][tr * 8];
            float4 xb = *(const float4*)&sXT[cur][kk][tr * 8 + 4];
            unsigned long long wp[4], xd[8];
            asm("mov.b64 %0, {%1, %2};" : "=l"(wp[0]) : "f"(w0.x), "f"(w0.y));
            asm("mov.b64 %0, {%1, %2};" : "=l"(wp[1]) : "f"(w0.z), "f"(w0.w));
            asm("mov.b64 %0, {%1, %2};" : "=l"(wp[2]) : "f"(w1.x), "f"(w1.y));
            asm("mov.b64 %0, {%1, %2};" : "=l"(wp[3]) : "f"(w1.z), "f"(w1.w));
            asm("mov.b64 %0, {%1, %1};" : "=l"(xd[0]) : "f"(xa.x));
            asm("mov.b64 %0, {%1, %1};" : "=l"(xd[1]) : "f"(xa.y));
            asm("mov.b64 %0, {%1, %1};" : "=l"(xd[2]) : "f"(xa.z));
            asm("mov.b64 %0, {%1, %1};" : "=l"(xd[3]) : "f"(xa.w));
            asm("mov.b64 %0, {%1, %1};" : "=l"(xd[4]) : "f"(xb.x));
            asm("mov.b64 %0, {%1, %1};" : "=l"(xd[5]) : "f"(xb.y));
            asm("mov.b64 %0, {%1, %1};" : "=l"(xd[6]) : "f"(xb.z));
            asm("mov.b64 %0, {%1, %1};" : "=l"(xd[7]) : "f"(xb.w));
#pragma unroll
            for (int r = 0; r < 8; r++)
#pragma unroll
                for (int c = 0; c < 4; c++)
                    asm("fma.rn.f32x2 %0, %1, %2, %3;"
                        : "=l"(acc[r][c]) : "l"(xd[r]), "l"(wp[c]), "l"(acc[r][c]));
        }

        if (ch < IN_DIM / BKC - 1) {
#pragma unroll
            for (int j = 0; j < 4; j++) {
                sXT[cur ^ 1][xc0 * 4 + j][xr0] = ((const float*)&nx0)[j];
                sXT[cur ^ 1][xc1 * 4 + j][xr1] = ((const float*)&nx1)[j];
            }
            asm volatile("cp.async.wait_group 0;" ::: "memory");
            __syncthreads();
        }
    }

    // epilogue: cols tc*8..+7 == attn[tc*8..+7] flattened (head = tc>>1)
    float al8[8], ar8[8];
    *(float4*)&al8[0] = *(const float4*)&attn_l[tc * 8];
    *(float4*)&al8[4] = *(const float4*)&attn_l[tc * 8 + 4];
    *(float4*)&ar8[0] = *(const float4*)&attn_r[tc * 8];
    *(float4*)&ar8[4] = *(const float4*)&attn_r[tc * 8 + 4];

#pragma unroll
    for (int r = 0; r < 8; r++) {
        float accf[8];
#pragma unroll
        for (int c = 0; c < 4; c++)
            asm("mov.b64 {%0, %1}, %2;"
                : "=f"(accf[2 * c]), "=f"(accf[2 * c + 1]) : "l"(acc[r][c]));
        int node = row0 + tr * 8 + r;
        bool ok = node < N_NODES;
        float pl = 0.f, pr = 0.f;
#pragma unroll
        for (int j = 0; j < 8; j++) {
            pl = fmaf(accf[j], al8[j], pl);
            pr = fmaf(accf[j], ar8[j], pr);
        }
        pl += __shfl_xor_sync(0xffffffffu, pl, 1);
        pr += __shfl_xor_sync(0xffffffffu, pr, 1);
        if (ok) {
            __half2 h2[4];
#pragma unroll
            for (int c = 0; c < 4; c++)
                h2[c] = __floats2half2_rn(accf[2 * c], accf[2 * c + 1]);
            *(uint2*)&g_feat_h[node * F + tc * 8]     = *(uint2*)&h2[0];
            *(uint2*)&g_feat_h[node * F + tc * 8 + 4] = *(uint2*)&h2[2];
            if ((tc & 1) == 0) {
                g_el[node * KH + (tc >> 1)] = pl;
                g_er[node * KH + (tc >> 1)] = pr;
            }
        }
    }
}

// ---------------- CSR build (rank-based, self-resetting) ----------------
__global__ void hist_kernel(const int* __restrict__ dst) {
    int e = blockIdx.x * blockDim.x + threadIdx.x;
    if (e >= E_EDGES) return;
    g_rank[e] = atomicAdd(&g_deg[dst[e]], 1);
}

__device__ __forceinline__ unsigned long long desc_ld(int idx) {
    unsigned long long v;
    asm volatile("ld.volatile.global.u64 %0, [%1];" : "=l"(v) : "l"(&g_desc[idx]));
    return v;
}
__device__ __forceinline__ void desc_st(int idx, unsigned long long v) {
    asm volatile("st.volatile.global.u64 [%0], %1;" :: "l"(&g_desc[idx]), "l"(v) : "memory");
}

__global__ __launch_bounds__(SCAN_B) void scan_kernel() {
    __shared__ int warp_sums[32];
    __shared__ int s_bprefix;
    int tid  = threadIdx.x;
    int lane = tid & 31;
    int wid  = tid >> 5;
    int b    = blockIdx.x;
    int gid  = b * SCAN_B + tid;
    int v = (gid < N_NODES) ? g_deg[gid] : 0;
    if (gid < N_NODES) g_deg[gid] = 0;

    int x = v;
#pragma unroll
    for (int d = 1; d < 32; d <<= 1) {
        int tv = __shfl_up_sync(0xffffffffu, x, d);
        if (lane >= d) x += tv;
    }
    if (lane == 31) warp_sums[wid] = x;
    __syncthreads();
    if (wid == 0) {
        int y = warp_sums[lane];
#pragma unroll
        for (int d = 1; d < 32; d <<= 1) {
            int tv = __shfl_up_sync(0xffffffffu, y, d);
            if (lane >= d) y += tv;
        }
        warp_sums[lane] = y;
    }
    __syncthreads();
    int block_total = warp_sums[31];
    int excl = ((wid > 0) ? warp_sums[wid - 1] : 0) + x - v;

    if (wid == 0) {
        if (b == 0) {
            if (lane == 0) {
                desc_st(0, (2ULL << 32) | (unsigned)block_total);
                s_bprefix = 0;
            }
        } else {
            if (lane == 0) desc_st(b, (1ULL << 32) | (unsigned)block_total);
            int prefix = 0;
            int look = b - 1;
            while (look >= 0) {
                int idx = look - lane;
                unsigned long long d = 0;
                if (idx >= 0) {
                    do { d = desc_ld(idx); } while ((d >> 32) == 0ULL);
                }
                unsigned st = (idx >= 0) ? (unsigned)(d >> 32) : 0u;
                unsigned mask2 = __ballot_sync(0xffffffffu, st == 2u);
                int stop = mask2 ? (__ffs(mask2) - 1) : 32;
                int contrib = (idx >= 0 && lane <= stop) ? (int)(d & 0xffffffffULL) : 0;
#pragma unroll
                for (int dd = 16; dd > 0; dd >>= 1)
                    contrib += __shfl_xor_sync(0xffffffffu, contrib, dd);
                prefix += contrib;
                if (mask2) break;
                look -= 32;
            }
            if (lane == 0) {
                desc_st(b, (2ULL << 32) | (unsigned)(prefix + block_total));
                s_bprefix = prefix;
            }
        }
    }
    __syncthreads();
    if (gid < N_NODES) g_off[gid] = s_bprefix + excl;
    if (b == 0 && tid == 0) g_off[N_NODES] = E_EDGES;
}

__global__ void scatter_kernel(const int* __restrict__ src,
                               const int* __restrict__ dst) {
    int e = blockIdx.x * blockDim.x + threadIdx.x;
    if (blockIdx.x == 0 && threadIdx.x < NBLK) g_desc[threadIdx.x] = 0ULL;
    if (e >= E_EDGES) return;
    g_psrc[g_off[dst[e]] + g_rank[e]] = src[e];
}

// ---------------- P3: single-pass warp-per-dst gather ----------------
__device__ __forceinline__ void edge_math(float elv, float er_k,
                                          unsigned long long pk,
                                          float4& acc, float& ssum) {
    float v = elv + er_k;
    v = (v > 0.f) ? v : NEG_SLOPE * v;
    float ex = __expf(v);
    ssum += ex;
    __half2 h0 = ((const __half2*)&pk)[0];
    __half2 h1 = ((const __half2*)&pk)[1];
    float2 f0 = __half22float2(h0);
    float2 f1 = __half22float2(h1);
    acc.x = fmaf(ex, f0.x, acc.x);
    acc.y = fmaf(ex, f0.y, acc.y);
    acc.z = fmaf(ex, f1.x, acc.z);
    acc.w = fmaf(ex, f1.y, acc.w);
}

__global__ __launch_bounds__(256) void agg_csr_kernel(float* __restrict__ out) {
    __shared__ int s_src[8][CAP];
    int wid  = threadIdx.x >> 5;
    int lane = threadIdx.x & 31;
    int w = blockIdx.x * 8 + wid;
    if (w >= N_NODES) return;
    int off0 = g_off[w];
    int off1 = g_off[w + 1];
    int deg  = off1 - off0;
    int cached = (deg < CAP) ? deg : CAP;

    for (int i = lane; i < cached; i += 32) s_src[wid][i] = __ldg(&g_psrc[off0 + i]);

    int khead = lane >> 2;
    float er_k = __ldg(&g_er[w * KH + khead]);
    __syncwarp();

    float4 acc = make_float4(0.f, 0.f, 0.f, 0.f);
    float ssum = 0.f;
    int i = 0;
    for (; i + 7 < cached; i += 8) {
        int s[8];
#pragma unroll
        for (int j = 0; j < 8; j++) s[j] = s_src[wid][i + j];
        float elv[8];
        unsigned long long pk[8];
#pragma unroll
        for (int j = 0; j < 8; j++) elv[j] = __ldg(&g_el[s[j] * KH + khead]);
#pragma unroll
        for (int j = 0; j < 8; j++)
            pk[j] = *(const unsigned long long*)&g_feat_h[s[j] * F + lane * 4];
#pragma unroll
        for (int j = 0; j < 8; j++) edge_math(elv[j], er_k, pk[j], acc, ssum);
    }
    for (; i < cached; i++) {
        int s = s_src[wid][i];
        float elv = __ldg(&g_el[s * KH + khead]);
        unsigned long long pk = *(const unsigned long long*)&g_feat_h[s * F + lane * 4];
        edge_math(elv, er_k, pk, acc, ssum);
    }
    for (; i < deg; i++) {
        int s = __ldg(&g_psrc[off0 + i]);
        float elv = __ldg(&g_el[s * KH + khead]);
        unsigned long long pk = *(const unsigned long long*)&g_feat_h[s * F + lane * 4];
        edge_math(elv, er_k, pk, acc, ssum);
    }

    float inv = (deg > 0) ? __fdividef(1.f, ssum) : 0.f;
    *(float4*)&out[w * F + lane * 4] =
        make_float4(acc.x * inv, acc.y * inv, acc.z * inv, acc.w * inv);
}

// ---------------- launch (CSR chain overlapped with GEMM) ----------------
extern "C" void kernel_launch(void* const* d_in, const int* in_sizes, int n_in,
                              void* d_out, int out_size) {
    const float* feat   = (const float*)d_in[0];
    const float* W      = (const float*)d_in[1];
    const float* attn_l = (const float*)d_in[2];
    const float* attn_r = (const float*)d_in[3];
    const int*   src    = (const int*)d_in[4];
    const int*   dst    = (const int*)d_in[5];
    float* out = (float*)d_out;

    static cudaStream_t s2 = nullptr;
    static cudaEvent_t evFork = nullptr, evCsr = nullptr;
    if (s2 == nullptr) {
        cudaStreamCreateWithFlags(&s2, cudaStreamNonBlocking);
        cudaEventCreateWithFlags(&evFork, cudaEventDisableTiming);
        cudaEventCreateWithFlags(&evCsr, cudaEventDisableTiming);
    }

    const int T = 256;
    cudaEventRecord(evFork, 0);
    cudaStreamWaitEvent(s2, evFork, 0);
    hist_kernel<<<(E_EDGES + T - 1) / T, T, 0, s2>>>(dst);
    scan_kernel<<<NBLK, SCAN_B, 0, s2>>>();
    scatter_kernel<<<(E_EDGES + T - 1) / T, T, 0, s2>>>(src, dst);
    cudaEventRecord(evCsr, s2);

    gemm_kernel<<<(N_NODES + 63) / 64, 128>>>(feat, W, attn_l, attn_r);

    cudaStreamWaitEvent(0, evCsr, 0);
    agg_csr_kernel<<<(N_NODES + 7) / 8, T>>>(out);
}

// round 14
// speedup vs baseline: 1.3031x; 1.3031x over previous
#include <cuda_runtime.h>
#include <cuda_fp16.h>
#include <cstdint>

#define N_NODES 100000
#define E_EDGES 1600000
#define IN_DIM  128
#define KH      8
#define DH      16
#define F       128
#define NEG_SLOPE 0.2f
#define SCAN_B  1024
#define NBLK    ((N_NODES + SCAN_B - 1) / SCAN_B)   // 98
#define CAP     128

// ---------------- scratch ----------------
__device__ __half g_feat_h[N_NODES * F];
__device__ __half g_W_h[F * IN_DIM];          // [n][k] fp16, transposed W
__device__ float  g_el[N_NODES * KH];
__device__ float  g_er[N_NODES * KH];
__device__ int    g_deg[N_NODES];
__device__ int    g_off[N_NODES + 1];
__device__ int    g_rank[E_EDGES];
__device__ int    g_psrc[E_EDGES];
__device__ unsigned long long g_desc[NBLK];

// ---------------- P0: transpose+convert W to fp16 [n][k] ----------------
__global__ void wprep_kernel(const float* __restrict__ W) {
    int i = blockIdx.x * 256 + threadIdx.x;
    if (i < IN_DIM * F) {
        int k = i >> 7, n = i & 127;
        g_W_h[n * IN_DIM + k] = __float2half(W[k * F + n]);
    }
}

// ---------------- P1: fp16 HMMA GEMM feat @ W + fused el/er ----------------
#define GBM 128
__global__ __launch_bounds__(256, 2) void gemm_kernel(const float* __restrict__ feat,
                                                      const float* __restrict__ attn_l,
                                                      const float* __restrict__ attn_r) {
    __shared__ __align__(16) __half sA[2][GBM][20];   // [row][k] pad 16->20
    __shared__ __align__(16) __half sB[2][F][20];     // [n][k]  pad 16->20
    const int t    = threadIdx.x;
    const int lane = t & 31;
    const int w    = t >> 5;
    const int g    = lane >> 2;
    const int tig  = lane & 3;
    const int wm   = w & 3;
    const int wn   = w >> 2;
    const int row0 = blockIdx.x * GBM;

    const int ar0 = t >> 2, ac0 = t & 3;
    const int ar1 = (t + 256) >> 2, ac1 = (t + 256) & 3;
    int ga0 = row0 + ar0; if (ga0 >= N_NODES) ga0 = N_NODES - 1;
    int ga1 = row0 + ar1; if (ga1 >= N_NODES) ga1 = N_NODES - 1;
    const int bn = t >> 1, bp = t & 1;

    float4 fa0 = *(const float4*)&feat[ga0 * IN_DIM + ac0 * 4];
    float4 fa1 = *(const float4*)&feat[ga1 * IN_DIM + ac1 * 4];
    uint4  fb  = *(const uint4*)&g_W_h[bn * IN_DIM + bp * 8];

    float cacc[2][8][4];
#pragma unroll
    for (int mt = 0; mt < 2; mt++)
#pragma unroll
        for (int nt = 0; nt < 8; nt++)
#pragma unroll
            for (int q = 0; q < 4; q++) cacc[mt][nt][q] = 0.f;

#pragma unroll
    for (int ch = 0; ch < 8; ch++) {
        const int cur = ch & 1;
        *(__half2*)&sA[cur][ar0][ac0 * 4]     = __floats2half2_rn(fa0.x, fa0.y);
        *(__half2*)&sA[cur][ar0][ac0 * 4 + 2] = __floats2half2_rn(fa0.z, fa0.w);
        *(__half2*)&sA[cur][ar1][ac1 * 4]     = __floats2half2_rn(fa1.x, fa1.y);
        *(__half2*)&sA[cur][ar1][ac1 * 4 + 2] = __floats2half2_rn(fa1.z, fa1.w);
        *(uint2*)&sB[cur][bn][bp * 8]     = make_uint2(fb.x, fb.y);
        *(uint2*)&sB[cur][bn][bp * 8 + 4] = make_uint2(fb.z, fb.w);
        __syncthreads();

        if (ch < 7) {
            int kb = (ch + 1) * 16;
            fa0 = *(const float4*)&feat[ga0 * IN_DIM + kb + ac0 * 4];
            fa1 = *(const float4*)&feat[ga1 * IN_DIM + kb + ac1 * 4];
            fb  = *(const uint4*)&g_W_h[bn * IN_DIM + kb + bp * 8];   // FIXED (was kb*2)
        }

        unsigned a[2][4];
#pragma unroll
        for (int mt = 0; mt < 2; mt++) {
            int rb = wm * 32 + mt * 16;
            a[mt][0] = *(const unsigned*)&sA[cur][rb + g][2 * tig];
            a[mt][1] = *(const unsigned*)&sA[cur][rb + g + 8][2 * tig];
            a[mt][2] = *(const unsigned*)&sA[cur][rb + g][2 * tig + 8];
            a[mt][3] = *(const unsigned*)&sA[cur][rb + g + 8][2 * tig + 8];
        }
#pragma unroll
        for (int nt = 0; nt < 8; nt++) {
            int cb = wn * 64 + nt * 8;
            unsigned b0 = *(const unsigned*)&sB[cur][cb + g][2 * tig];
            unsigned b1 = *(const unsigned*)&sB[cur][cb + g][2 * tig + 8];
#pragma unroll
            for (int mt = 0; mt < 2; mt++)
                asm volatile("mma.sync.aligned.m16n8k16.row.col.f32.f16.f16.f32 "
                    "{%0,%1,%2,%3}, {%4,%5,%6,%7}, {%8,%9}, {%0,%1,%2,%3};"
                    : "+f"(cacc[mt][nt][0]), "+f"(cacc[mt][nt][1]),
                      "+f"(cacc[mt][nt][2]), "+f"(cacc[mt][nt][3])
                    : "r"(a[mt][0]), "r"(a[mt][1]), "r"(a[mt][2]), "r"(a[mt][3]),
                      "r"(b0), "r"(b1));
        }
    }

    // epilogue
    const int colbase = wn * 64;
    float2 al2[8], ar2[8];
#pragma unroll
    for (int nt = 0; nt < 8; nt++) {
        al2[nt] = *(const float2*)&attn_l[colbase + nt * 8 + 2 * tig];
        ar2[nt] = *(const float2*)&attn_r[colbase + nt * 8 + 2 * tig];
    }
#pragma unroll
    for (int mt = 0; mt < 2; mt++)
#pragma unroll
        for (int h = 0; h < 2; h++) {
            int node = row0 + wm * 32 + mt * 16 + h * 8 + g;
            bool ok = node < N_NODES;
            float pl[4] = {0.f, 0.f, 0.f, 0.f};
            float pr[4] = {0.f, 0.f, 0.f, 0.f};
#pragma unroll
            for (int nt = 0; nt < 8; nt++) {
                float c0 = cacc[mt][nt][h * 2 + 0];
                float c1 = cacc[mt][nt][h * 2 + 1];
                if (ok)
                    *(__half2*)&g_feat_h[node * F + colbase + nt * 8 + 2 * tig] =
                        __floats2half2_rn(c0, c1);
                int hd = nt >> 1;
                pl[hd] = fmaf(c0, al2[nt].x, fmaf(c1, al2[nt].y, pl[hd]));
                pr[hd] = fmaf(c0, ar2[nt].x, fmaf(c1, ar2[nt].y, pr[hd]));
            }
#pragma unroll
            for (int hd = 0; hd < 4; hd++) {
                pl[hd] += __shfl_xor_sync(0xffffffffu, pl[hd], 1);
                pl[hd] += __shfl_xor_sync(0xffffffffu, pl[hd], 2);
                pr[hd] += __shfl_xor_sync(0xffffffffu, pr[hd], 1);
                pr[hd] += __shfl_xor_sync(0xffffffffu, pr[hd], 2);
                if (ok && tig == 0) {
                    g_el[node * KH + wn * 4 + hd] = pl[hd];
                    g_er[node * KH + wn * 4 + hd] = pr[hd];
                }
            }
        }
}

// ---------------- CSR build (rank-based, self-resetting) ----------------
__global__ void hist_kernel(const int* __restrict__ dst) {
    int e = blockIdx.x * blockDim.x + threadIdx.x;
    if (e >= E_EDGES) return;
    g_rank[e] = atomicAdd(&g_deg[dst[e]], 1);
}

__device__ __forceinline__ unsigned long long desc_ld(int idx) {
    unsigned long long v;
    asm volatile("ld.volatile.global.u64 %0, [%1];" : "=l"(v) : "l"(&g_desc[idx]));
    return v;
}
__device__ __forceinline__ void desc_st(int idx, unsigned long long v) {
    asm volatile("st.volatile.global.u64 [%0], %1;" :: "l"(&g_desc[idx]), "l"(v) : "memory");
}

__global__ __launch_bounds__(SCAN_B) void scan_kernel() {
    __shared__ int warp_sums[32];
    __shared__ int s_bprefix;
    int tid  = threadIdx.x;
    int lane = tid & 31;
    int wid  = tid >> 5;
    int b    = blockIdx.x;
    int gid  = b * SCAN_B + tid;
    int v = (gid < N_NODES) ? g_deg[gid] : 0;
    if (gid < N_NODES) g_deg[gid] = 0;

    int x = v;
#pragma unroll
    for (int d = 1; d < 32; d <<= 1) {
        int tv = __shfl_up_sync(0xffffffffu, x, d);
        if (lane >= d) x += tv;
    }
    if (lane == 31) warp_sums[wid] = x;
    __syncthreads();
    if (wid == 0) {
        int y = warp_sums[lane];
#pragma unroll
        for (int d = 1; d < 32; d <<= 1) {
            int tv = __shfl_up_sync(0xffffffffu, y, d);
            if (lane >= d) y += tv;
        }
        warp_sums[lane] = y;
    }
    __syncthreads();
    int block_total = warp_sums[31];
    int excl = ((wid > 0) ? warp_sums[wid - 1] : 0) + x - v;

    if (wid == 0) {
        if (b == 0) {
            if (lane == 0) {
                desc_st(0, (2ULL << 32) | (unsigned)block_total);
                s_bprefix = 0;
            }
        } else {
            if (lane == 0) desc_st(b, (1ULL << 32) | (unsigned)block_total);
            int prefix = 0;
            int look = b - 1;
            while (look >= 0) {
                int idx = look - lane;
                unsigned long long d = 0;
                if (idx >= 0) {
                    do { d = desc_ld(idx); } while ((d >> 32) == 0ULL);
                }
                unsigned st = (idx >= 0) ? (unsigned)(d >> 32) : 0u;
                unsigned mask2 = __ballot_sync(0xffffffffu, st == 2u);
                int stop = mask2 ? (__ffs(mask2) - 1) : 32;
                int contrib = (idx >= 0 && lane <= stop) ? (int)(d & 0xffffffffULL) : 0;
#pragma unroll
                for (int dd = 16; dd > 0; dd >>= 1)
                    contrib += __shfl_xor_sync(0xffffffffu, contrib, dd);
                prefix += contrib;
                if (mask2) break;
                look -= 32;
            }
            if (lane == 0) {
                desc_st(b, (2ULL << 32) | (unsigned)(prefix + block_total));
                s_bprefix = prefix;
            }
        }
    }
    __syncthreads();
    if (gid < N_NODES) g_off[gid] = s_bprefix + excl;
    if (b == 0 && tid == 0) g_off[N_NODES] = E_EDGES;
}

__global__ void scatter_kernel(const int* __restrict__ src,
                               const int* __restrict__ dst) {
    int e = blockIdx.x * blockDim.x + threadIdx.x;
    if (blockIdx.x == 0 && threadIdx.x < NBLK) g_desc[threadIdx.x] = 0ULL;
    if (e >= E_EDGES) return;
    g_psrc[g_off[dst[e]] + g_rank[e]] = src[e];
}

// ---------------- P3: single-pass warp-per-dst gather ----------------
__device__ __forceinline__ void edge_math(float elv, float er_k,
                                          unsigned long long pk,
                                          float4& acc, float& ssum) {
    float v = elv + er_k;
    v = (v > 0.f) ? v : NEG_SLOPE * v;
    float ex = __expf(v);
    ssum += ex;
    __half2 h0 = ((const __half2*)&pk)[0];
    __half2 h1 = ((const __half2*)&pk)[1];
    float2 f0 = __half22float2(h0);
    float2 f1 = __half22float2(h1);
    acc.x = fmaf(ex, f0.x, acc.x);
    acc.y = fmaf(ex, f0.y, acc.y);
    acc.z = fmaf(ex, f1.x, acc.z);
    acc.w = fmaf(ex, f1.y, acc.w);
}

__global__ __launch_bounds__(256) void agg_csr_kernel(float* __restrict__ out) {
    __shared__ int s_src[8][CAP];
    int wid  = threadIdx.x >> 5;
    int lane = threadIdx.x & 31;
    int w = blockIdx.x * 8 + wid;
    if (w >= N_NODES) return;
    int off0 = g_off[w];
    int off1 = g_off[w + 1];
    int deg  = off1 - off0;
    int cached = (deg < CAP) ? deg : CAP;

    for (int i = lane; i < cached; i += 32) s_src[wid][i] = __ldg(&g_psrc[off0 + i]);

    int khead = lane >> 2;
    float er_k = __ldg(&g_er[w * KH + khead]);
    __syncwarp();

    float4 acc = make_float4(0.f, 0.f, 0.f, 0.f);
    float ssum = 0.f;
    int i = 0;
    for (; i + 7 < cached; i += 8) {
        int s[8];
#pragma unroll
        for (int j = 0; j < 8; j++) s[j] = s_src[wid][i + j];
        float elv[8];
        unsigned long long pk[8];
#pragma unroll
        for (int j = 0; j < 8; j++) elv[j] = __ldg(&g_el[s[j] * KH + khead]);
#pragma unroll
        for (int j = 0; j < 8; j++)
            pk[j] = *(const unsigned long long*)&g_feat_h[s[j] * F + lane * 4];
#pragma unroll
        for (int j = 0; j < 8; j++) edge_math(elv[j], er_k, pk[j], acc, ssum);
    }
    for (; i < cached; i++) {
        int s = s_src[wid][i];
        float elv = __ldg(&g_el[s * KH + khead]);
        unsigned long long pk = *(const unsigned long long*)&g_feat_h[s * F + lane * 4];
        edge_math(elv, er_k, pk, acc, ssum);
    }
    for (; i < deg; i++) {
        int s = __ldg(&g_psrc[off0 + i]);
        float elv = __ldg(&g_el[s * KH + khead]);
        unsigned long long pk = *(const unsigned long long*)&g_feat_h[s * F + lane * 4];
        edge_math(elv, er_k, pk, acc, ssum);
    }

    float inv = (deg > 0) ? __fdividef(1.f, ssum) : 0.f;
    *(float4*)&out[w * F + lane * 4] =
        make_float4(acc.x * inv, acc.y * inv, acc.z * inv, acc.w * inv);
}

// ---------------- launch (CSR chain overlapped with GEMM) ----------------
extern "C" void kernel_launch(void* const* d_in, const int* in_sizes, int n_in,
                              void* d_out, int out_size) {
    const float* feat   = (const float*)d_in[0];
    const float* W      = (const float*)d_in[1];
    const float* attn_l = (const float*)d_in[2];
    const float* attn_r = (const float*)d_in[3];
    const int*   src    = (const int*)d_in[4];
    const int*   dst    = (const int*)d_in[5];
    float* out = (float*)d_out;

    static cudaStream_t s2 = nullptr;
    static cudaEvent_t evFork = nullptr, evCsr = nullptr;
    if (s2 == nullptr) {
        cudaStreamCreateWithFlags(&s2, cudaStreamNonBlocking);
        cudaEventCreateWithFlags(&evFork, cudaEventDisableTiming);
        cudaEventCreateWithFlags(&evCsr, cudaEventDisableTiming);
    }

    const int T = 256;
    cudaEventRecord(evFork, 0);
    cudaStreamWaitEvent(s2, evFork, 0);
    hist_kernel<<<(E_EDGES + T - 1) / T, T, 0, s2>>>(dst);
    scan_kernel<<<NBLK, SCAN_B, 0, s2>>>();
    scatter_kernel<<<(E_EDGES + T - 1) / T, T, 0, s2>>>(src, dst);
    cudaEventRecord(evCsr, s2);

    wprep_kernel<<<(IN_DIM * F + T - 1) / T, T>>>(W);
    gemm_kernel<<<(N_NODES + GBM - 1) / GBM, T>>>(feat, attn_l, attn_r);

    cudaStreamWaitEvent(0, evCsr, 0);
    agg_csr_kernel<<<(N_NODES + 7) / 8, T>>>(out);
}

// round 15
// speedup vs baseline: 1.3662x; 1.0485x over previous
#include <cuda_runtime.h>
#include <cuda_fp16.h>
#include <cstdint>

#define N_NODES 100000
#define E_EDGES 1600000
#define IN_DIM  128
#define KH      8
#define DH      16
#define F       128
#define NEG_SLOPE 0.2f
#define SCAN_B  1024
#define NBLK    ((N_NODES + SCAN_B - 1) / SCAN_B)   // 98
#define CAP     128

// ---------------- scratch ----------------
__device__ __half g_feat_h[N_NODES * F];
__device__ __half g_W_h[F * IN_DIM];          // [n][k] fp16, transposed W
__device__ float  g_el[N_NODES * KH];
__device__ float  g_er[N_NODES * KH];
__device__ int    g_deg[N_NODES];
__device__ int    g_off[N_NODES + 1];
__device__ int    g_rank[E_EDGES];
__device__ int    g_psrc[E_EDGES];
__device__ unsigned long long g_desc[NBLK];

// ---------------- P0: transpose+convert W to fp16 [n][k] ----------------
__global__ void wprep_kernel(const float* __restrict__ W) {
    int i = blockIdx.x * 256 + threadIdx.x;
    if (i < IN_DIM * F) {
        int k = i >> 7, n = i & 127;
        g_W_h[n * IN_DIM + k] = __float2half(W[k * F + n]);
    }
}

// ---------------- P1: fp16 HMMA GEMM feat @ W + fused el/er ----------------
#define GBM 128
__global__ __launch_bounds__(256, 2) void gemm_kernel(const float* __restrict__ feat,
                                                      const float* __restrict__ attn_l,
                                                      const float* __restrict__ attn_r) {
    __shared__ __align__(16) __half sA[2][GBM][20];
    __shared__ __align__(16) __half sB[2][F][20];
    const int t    = threadIdx.x;
    const int lane = t & 31;
    const int w    = t >> 5;
    const int g    = lane >> 2;
    const int tig  = lane & 3;
    const int wm   = w & 3;
    const int wn   = w >> 2;
    const int row0 = blockIdx.x * GBM;

    const int ar0 = t >> 2, ac0 = t & 3;
    const int ar1 = (t + 256) >> 2, ac1 = (t + 256) & 3;
    int ga0 = row0 + ar0; if (ga0 >= N_NODES) ga0 = N_NODES - 1;
    int ga1 = row0 + ar1; if (ga1 >= N_NODES) ga1 = N_NODES - 1;
    const int bn = t >> 1, bp = t & 1;

    float4 fa0 = *(const float4*)&feat[ga0 * IN_DIM + ac0 * 4];
    float4 fa1 = *(const float4*)&feat[ga1 * IN_DIM + ac1 * 4];
    uint4  fb  = *(const uint4*)&g_W_h[bn * IN_DIM + bp * 8];

    float cacc[2][8][4];
#pragma unroll
    for (int mt = 0; mt < 2; mt++)
#pragma unroll
        for (int nt = 0; nt < 8; nt++)
#pragma unroll
            for (int q = 0; q < 4; q++) cacc[mt][nt][q] = 0.f;

#pragma unroll
    for (int ch = 0; ch < 8; ch++) {
        const int cur = ch & 1;
        *(__half2*)&sA[cur][ar0][ac0 * 4]     = __floats2half2_rn(fa0.x, fa0.y);
        *(__half2*)&sA[cur][ar0][ac0 * 4 + 2] = __floats2half2_rn(fa0.z, fa0.w);
        *(__half2*)&sA[cur][ar1][ac1 * 4]     = __floats2half2_rn(fa1.x, fa1.y);
        *(__half2*)&sA[cur][ar1][ac1 * 4 + 2] = __floats2half2_rn(fa1.z, fa1.w);
        *(uint2*)&sB[cur][bn][bp * 8]     = make_uint2(fb.x, fb.y);
        *(uint2*)&sB[cur][bn][bp * 8 + 4] = make_uint2(fb.z, fb.w);
        __syncthreads();

        if (ch < 7) {
            int kb = (ch + 1) * 16;
            fa0 = *(const float4*)&feat[ga0 * IN_DIM + kb + ac0 * 4];
            fa1 = *(const float4*)&feat[ga1 * IN_DIM + kb + ac1 * 4];
            fb  = *(const uint4*)&g_W_h[bn * IN_DIM + kb + bp * 8];
        }

        unsigned a[2][4];
#pragma unroll
        for (int mt = 0; mt < 2; mt++) {
            int rb = wm * 32 + mt * 16;
            a[mt][0] = *(const unsigned*)&sA[cur][rb + g][2 * tig];
            a[mt][1] = *(const unsigned*)&sA[cur][rb + g + 8][2 * tig];
            a[mt][2] = *(const unsigned*)&sA[cur][rb + g][2 * tig + 8];
            a[mt][3] = *(const unsigned*)&sA[cur][rb + g + 8][2 * tig + 8];
        }
#pragma unroll
        for (int nt = 0; nt < 8; nt++) {
            int cb = wn * 64 + nt * 8;
            unsigned b0 = *(const unsigned*)&sB[cur][cb + g][2 * tig];
            unsigned b1 = *(const unsigned*)&sB[cur][cb + g][2 * tig + 8];
#pragma unroll
            for (int mt = 0; mt < 2; mt++)
                asm volatile("mma.sync.aligned.m16n8k16.row.col.f32.f16.f16.f32 "
                    "{%0,%1,%2,%3}, {%4,%5,%6,%7}, {%8,%9}, {%0,%1,%2,%3};"
                    : "+f"(cacc[mt][nt][0]), "+f"(cacc[mt][nt][1]),
                      "+f"(cacc[mt][nt][2]), "+f"(cacc[mt][nt][3])
                    : "r"(a[mt][0]), "r"(a[mt][1]), "r"(a[mt][2]), "r"(a[mt][3]),
                      "r"(b0), "r"(b1));
        }
    }

    const int colbase = wn * 64;
    float2 al2[8], ar2[8];
#pragma unroll
    for (int nt = 0; nt < 8; nt++) {
        al2[nt] = *(const float2*)&attn_l[colbase + nt * 8 + 2 * tig];
        ar2[nt] = *(const float2*)&attn_r[colbase + nt * 8 + 2 * tig];
    }
#pragma unroll
    for (int mt = 0; mt < 2; mt++)
#pragma unroll
        for (int h = 0; h < 2; h++) {
            int node = row0 + wm * 32 + mt * 16 + h * 8 + g;
            bool ok = node < N_NODES;
            float pl[4] = {0.f, 0.f, 0.f, 0.f};
            float pr[4] = {0.f, 0.f, 0.f, 0.f};
#pragma unroll
            for (int nt = 0; nt < 8; nt++) {
                float c0 = cacc[mt][nt][h * 2 + 0];
                float c1 = cacc[mt][nt][h * 2 + 1];
                if (ok)
                    *(__half2*)&g_feat_h[node * F + colbase + nt * 8 + 2 * tig] =
                        __floats2half2_rn(c0, c1);
                int hd = nt >> 1;
                pl[hd] = fmaf(c0, al2[nt].x, fmaf(c1, al2[nt].y, pl[hd]));
                pr[hd] = fmaf(c0, ar2[nt].x, fmaf(c1, ar2[nt].y, pr[hd]));
            }
#pragma unroll
            for (int hd = 0; hd < 4; hd++) {
                pl[hd] += __shfl_xor_sync(0xffffffffu, pl[hd], 1);
                pl[hd] += __shfl_xor_sync(0xffffffffu, pl[hd], 2);
                pr[hd] += __shfl_xor_sync(0xffffffffu, pr[hd], 1);
                pr[hd] += __shfl_xor_sync(0xffffffffu, pr[hd], 2);
                if (ok && tig == 0) {
                    g_el[node * KH + wn * 4 + hd] = pl[hd];
                    g_er[node * KH + wn * 4 + hd] = pr[hd];
                }
            }
        }
}

// ---------------- CSR build (rank-based, self-resetting) ----------------
__global__ void hist_kernel(const int* __restrict__ dst) {
    int e = blockIdx.x * blockDim.x + threadIdx.x;
    if (e >= E_EDGES) return;
    g_rank[e] = atomicAdd(&g_deg[dst[e]], 1);
}

__device__ __forceinline__ unsigned long long desc_ld(int idx) {
    unsigned long long v;
    asm volatile("ld.volatile.global.u64 %0, [%1];" : "=l"(v) : "l"(&g_desc[idx]));
    return v;
}
__device__ __forceinline__ void desc_st(int idx, unsigned long long v) {
    asm volatile("st.volatile.global.u64 [%0], %1;" :: "l"(&g_desc[idx]), "l"(v) : "memory");
}

__global__ __launch_bounds__(SCAN_B) void scan_kernel() {
    __shared__ int warp_sums[32];
    __shared__ int s_bprefix;
    int tid  = threadIdx.x;
    int lane = tid & 31;
    int wid  = tid >> 5;
    int b    = blockIdx.x;
    int gid  = b * SCAN_B + tid;
    int v = (gid < N_NODES) ? g_deg[gid] : 0;
    if (gid < N_NODES) g_deg[gid] = 0;

    int x = v;
#pragma unroll
    for (int d = 1; d < 32; d <<= 1) {
        int tv = __shfl_up_sync(0xffffffffu, x, d);
        if (lane >= d) x += tv;
    }
    if (lane == 31) warp_sums[wid] = x;
    __syncthreads();
    if (wid == 0) {
        int y = warp_sums[lane];
#pragma unroll
        for (int d = 1; d < 32; d <<= 1) {
            int tv = __shfl_up_sync(0xffffffffu, y, d);
            if (lane >= d) y += tv;
        }
        warp_sums[lane] = y;
    }
    __syncthreads();
    int block_total = warp_sums[31];
    int excl = ((wid > 0) ? warp_sums[wid - 1] : 0) + x - v;

    if (wid == 0) {
        if (b == 0) {
            if (lane == 0) {
                desc_st(0, (2ULL << 32) | (unsigned)block_total);
                s_bprefix = 0;
            }
        } else {
            if (lane == 0) desc_st(b, (1ULL << 32) | (unsigned)block_total);
            int prefix = 0;
            int look = b - 1;
            while (look >= 0) {
                int idx = look - lane;
                unsigned long long d = 0;
                if (idx >= 0) {
                    do { d = desc_ld(idx); } while ((d >> 32) == 0ULL);
                }
                unsigned st = (idx >= 0) ? (unsigned)(d >> 32) : 0u;
                unsigned mask2 = __ballot_sync(0xffffffffu, st == 2u);
                int stop = mask2 ? (__ffs(mask2) - 1) : 32;
                int contrib = (idx >= 0 && lane <= stop) ? (int)(d & 0xffffffffULL) : 0;
#pragma unroll
                for (int dd = 16; dd > 0; dd >>= 1)
                    contrib += __shfl_xor_sync(0xffffffffu, contrib, dd);
                prefix += contrib;
                if (mask2) break;
                look -= 32;
            }
            if (lane == 0) {
                desc_st(b, (2ULL << 32) | (unsigned)(prefix + block_total));
                s_bprefix = prefix;
            }
        }
    }
    __syncthreads();
    if (gid < N_NODES) g_off[gid] = s_bprefix + excl;
    if (b == 0 && tid == 0) g_off[N_NODES] = E_EDGES;
}

__global__ void scatter_kernel(const int* __restrict__ src,
                               const int* __restrict__ dst) {
    int e = blockIdx.x * blockDim.x + threadIdx.x;
    if (blockIdx.x == 0 && threadIdx.x < NBLK) g_desc[threadIdx.x] = 0ULL;
    if (e >= E_EDGES) return;
    g_psrc[g_off[dst[e]] + g_rank[e]] = src[e];
}

// ---------------- P3: agg, 16 lanes per edge, 2 edges per warp ----------------
// lane = half*16 + hl; lane covers fp16 features [hl*8 .. hl*8+7] (head = hl>>1).
// group 'half' processes edges i+half, i+2+half, ...; combine via shfl_xor(16).
__device__ __forceinline__ void edge_math16(float elv, float er_k, uint4 pk,
                                            float* acc, float& ssum) {
    float v = elv + er_k;
    v = (v > 0.f) ? v : NEG_SLOPE * v;
    float ex = __expf(v);
    ssum += ex;
    const __half2* h = (const __half2*)&pk;
#pragma unroll
    for (int m = 0; m < 4; m++) {
        float2 f = __half22float2(h[m]);
        acc[2 * m]     = fmaf(ex, f.x, acc[2 * m]);
        acc[2 * m + 1] = fmaf(ex, f.y, acc[2 * m + 1]);
    }
}

__global__ __launch_bounds__(256) void agg_csr_kernel(float* __restrict__ out) {
    __shared__ int s_src[8][CAP];
    int wid  = threadIdx.x >> 5;
    int lane = threadIdx.x & 31;
    int half = lane >> 4;          // 0/1 : edge parity group
    int hl   = lane & 15;          // position within group
    int head = hl >> 1;
    int w = blockIdx.x * 8 + wid;
    if (w >= N_NODES) return;
    int off0 = g_off[w];
    int off1 = g_off[w + 1];
    int deg  = off1 - off0;
    int cached = (deg < CAP) ? deg : CAP;

    for (int i = lane; i < cached; i += 32) s_src[wid][i] = __ldg(&g_psrc[off0 + i]);

    float er_k = __ldg(&g_er[w * KH + head]);
    __syncwarp();

    float acc[8];
#pragma unroll
    for (int m = 0; m < 8; m++) acc[m] = 0.f;
    float ssum = 0.f;

    int i = 0;
    // batch: 8 edges (4 per group), all loads batched for MLP
    for (; i + 7 < cached; i += 8) {
        int s[4];
#pragma unroll
        for (int j = 0; j < 4; j++) s[j] = s_src[wid][i + half + 2 * j];
        float elv[4];
#pragma unroll
        for (int j = 0; j < 4; j++) elv[j] = __ldg(&g_el[s[j] * KH + head]);
        uint4 pk[4];
#pragma unroll
        for (int j = 0; j < 4; j++)
            pk[j] = *(const uint4*)&g_feat_h[s[j] * F + hl * 8];
#pragma unroll
        for (int j = 0; j < 4; j++) edge_math16(elv[j], er_k, pk[j], acc, ssum);
    }
    // cached tail (pairs; guard parity)
    for (; i < cached; i += 2) {
        int e = i + half;
        if (e < cached) {
            int s = s_src[wid][e];
            float elv = __ldg(&g_el[s * KH + head]);
            uint4 pk = *(const uint4*)&g_feat_h[s * F + hl * 8];
            edge_math16(elv, er_k, pk, acc, ssum);
        }
    }
    // beyond CAP fallback
    for (i = cached + ((cached & 1) ? 0 : 0); i < deg; i += 2) {
        int e = i + half;
        if (e >= cached && e < deg) {
            int s = __ldg(&g_psrc[off0 + e]);
            float elv = __ldg(&g_el[s * KH + head]);
            uint4 pk = *(const uint4*)&g_feat_h[s * F + hl * 8];
            edge_math16(elv, er_k, pk, acc, ssum);
        }
    }

    // combine the two edge-parity groups
#pragma unroll
    for (int m = 0; m < 8; m++) acc[m] += __shfl_xor_sync(0xffffffffu, acc[m], 16);
    ssum += __shfl_xor_sync(0xffffffffu, ssum, 16);

    float inv = (deg > 0) ? __fdividef(1.f, ssum) : 0.f;
    float4 o = make_float4(acc[half * 4] * inv, acc[half * 4 + 1] * inv,
                           acc[half * 4 + 2] * inv, acc[half * 4 + 3] * inv);
    *(float4*)&out[w * F + hl * 8 + half * 4] = o;
}

// ---------------- launch (CSR chain overlapped with GEMM) ----------------
extern "C" void kernel_launch(void* const* d_in, const int* in_sizes, int n_in,
                              void* d_out, int out_size) {
    const float* feat   = (const float*)d_in[0];
    const float* W      = (const float*)d_in[1];
    const float* attn_l = (const float*)d_in[2];
    const float* attn_r = (const float*)d_in[3];
    const int*   src    = (const int*)d_in[4];
    const int*   dst    = (const int*)d_in[5];
    float* out = (float*)d_out;

    static cudaStream_t s2 = nullptr;
    static cudaEvent_t evFork = nullptr, evCsr = nullptr;
    if (s2 == nullptr) {
        cudaStreamCreateWithFlags(&s2, cudaStreamNonBlocking);
        cudaEventCreateWithFlags(&evFork, cudaEventDisableTiming);
        cudaEventCreateWithFlags(&evCsr, cudaEventDisableTiming);
    }

    const int T = 256;
    cudaEventRecord(evFork, 0);
    cudaStreamWaitEvent(s2, evFork, 0);
    hist_kernel<<<(E_EDGES + T - 1) / T, T, 0, s2>>>(dst);
    scan_kernel<<<NBLK, SCAN_B, 0, s2>>>();
    scatter_kernel<<<(E_EDGES + T - 1) / T, T, 0, s2>>>(src, dst);
    cudaEventRecord(evCsr, s2);

    wprep_kernel<<<(IN_DIM * F + T - 1) / T, T>>>(W);
    gemm_kernel<<<(N_NODES + GBM - 1) / GBM, T>>>(feat, attn_l, attn_r);

    cudaStreamWaitEvent(0, evCsr, 0);
    agg_csr_kernel<<<(N_NODES + 7) / 8, T>>>(out);
}